// round 13
// baseline (speedup 1.0000x reference)
#include <cuda_runtime.h>
#include <math.h>
#include <stdint.h>

#define B_  2
#define S_  2048
#define E_  1024
#define H_  16
#define HD_ 64

// Scratch (allocation-free: __device__ globals)
__device__ float g_Q[B_*H_*S_*HD_];   // (b,h,s,d) tf32-rounded, scaled 0.125*log2(e)
__device__ float g_K[B_*H_*S_*HD_];   // (b,h,s,d) tf32-rounded, d 16-block-permuted
__device__ float g_V[B_*H_*S_*HD_];   // (b,h,d,s) TRANSPOSED, s 16-block-permuted
__device__ float g_O[B_*S_*E_];       // attention out, tf32-rounded, d 16-block-permuted
__device__ float g_Xr[B_*S_*E_];      // tf32-rounded x, k-chunk permuted
__device__ float g_Wq[3*E_*E_];       // tf32-rounded w_qkv, k-chunk permuted
__device__ float g_Wp[E_*E_];         // tf32-rounded w_proj, k-chunk permuted

// ============================================================================
// PTX helpers (plain sm_80+ ISA)
// ============================================================================
__device__ __forceinline__ float tf32_rna(float x) {
    uint32_t r;
    asm("cvt.rna.tf32.f32 %0, %1;" : "=r"(r) : "f"(x));
    return __uint_as_float(r);
}

__device__ __forceinline__ void mma_tf32(float4& d,
                                         uint32_t a0, uint32_t a1, uint32_t a2, uint32_t a3,
                                         uint32_t b0, uint32_t b1)
{
    asm volatile(
        "mma.sync.aligned.m16n8k8.row.col.f32.tf32.tf32.f32 "
        "{%0,%1,%2,%3}, {%4,%5,%6,%7}, {%8,%9}, {%0,%1,%2,%3};"
        : "+f"(d.x), "+f"(d.y), "+f"(d.z), "+f"(d.w)
        : "r"(a0), "r"(a1), "r"(a2), "r"(a3), "r"(b0), "r"(b1));
}

__device__ __forceinline__ uint32_t smem_u32(const void* p) {
    uint32_t a;
    asm("{ .reg .u64 tmp; cvta.to.shared.u64 tmp, %1; cvt.u32.u64 %0, tmp; }"
        : "=r"(a) : "l"(p));
    return a;
}

__device__ __forceinline__ void cp16(uint32_t dst, const void* src) {
    asm volatile("cp.async.cg.shared.global [%0], [%1], 16;"
                 :: "r"(dst), "l"(src) : "memory");
}
#define CP_COMMIT() asm volatile("cp.async.commit_group;" ::: "memory")
#define CP_WAIT0()  asm volatile("cp.async.wait_group 0;" ::: "memory")
#define CP_WAIT1()  asm volatile("cp.async.wait_group 1;" ::: "memory")

// exp2 on the FMA pipe: degree-6 poly on f in [-0.5, 0.5], rel err ~1.2e-7.
__device__ __forceinline__ float exp2p(float x) {
    x = fmaxf(x, -126.0f);
    float n = rintf(x);
    float f = x - n;
    float p = 1.5403530e-4f;
    p = fmaf(p, f, 1.3333558e-3f);
    p = fmaf(p, f, 9.6181291e-3f);
    p = fmaf(p, f, 5.5504109e-2f);
    p = fmaf(p, f, 2.4022651e-1f);
    p = fmaf(p, f, 6.9314718e-1f);
    p = fmaf(p, f, 1.0f);
    float s = __int_as_float(((int)n + 127) << 23);
    return p * s;
}

// pi(m) = (m%4)*4 + m/4 applied within a 16-aligned block (self-inverse)
__device__ __forceinline__ int perm16(int c) {
    return (c & ~15) + ((c & 3) * 4) + ((c & 15) >> 2);
}

// ============================================================================
// Pre-pass: tf32-round AND k-chunk-permute all three GEMM inputs.
// ============================================================================
#define N4_X  ((B_*S_*E_) / 4)
#define N4_WQ ((3*E_*E_) / 4)
#define N4_WP ((E_*E_) / 4)
#define N4_ALL (N4_X + N4_WQ + N4_WP)

__global__ void round_perm_all(const float* __restrict__ x,
                               const float* __restrict__ wq,
                               const float* __restrict__ wp)
{
    int f = blockIdx.x * blockDim.x + threadIdx.x;
    const int stride = gridDim.x * blockDim.x;
    for (; f < N4_ALL; f += stride) {
        const float* s;
        float4* d;
        int i = f;
        if (i < N4_X)               { s = x;  d = (float4*)g_Xr; }
        else if (i < N4_X + N4_WQ)  { i -= N4_X;         s = wq; d = (float4*)g_Wq; }
        else                        { i -= N4_X + N4_WQ; s = wp; d = (float4*)g_Wp; }
        const int t    = i & 3;
        const int base = (i >> 2) << 4;
        float4 v;
        v.x = tf32_rna(s[base + t]);
        v.y = tf32_rna(s[base + t + 4]);
        v.z = tf32_rna(s[base + t + 8]);
        v.w = tf32_rna(s[base + t + 12]);
        d[i] = v;
    }
}

// ============================================================================
// TF32 warp-MMA GEMM (round-10 verified): BK=32, 3-stage cp.async, one sync
// per chunk. CTA 128x64, 8 warps 4x2, warp 32x32. Both operands permuted.
// ============================================================================
#define NSTG3 3
#define HALF_F 3072
#define STGF32 (2*HALF_F)
#define GEMM_SMEM_BYTES (NSTG3*STGF32*4)  // 73728

__device__ __forceinline__ void gemm_fill32(uint32_t smu, const float* __restrict__ Ab,
                                            const float* __restrict__ Bb,
                                            int stage, int chunk, int tid)
{
#pragma unroll
    for (int j = 0; j < 6; j++) {
        const int o = tid + 256 * j;
        const int h = (o >> 2) & 1;
        const int r = o >> 3;
        const int q = (o & 3) * 4;
        const float* src;
        uint32_t off;
        if (r < 128) {
            src = Ab + (size_t)r * 1024 + chunk * 32 + h * 16 + q;
            off = (uint32_t)(r * 16);
        } else {
            src = Bb + (size_t)(r - 128) * 1024 + chunk * 32 + h * 16 + q;
            off = (uint32_t)(2048 + (r - 128) * 16);
        }
        cp16(smu + (uint32_t)(stage * STGF32 + h * HALF_F + off + q) * 4, src);
    }
}

__device__ __forceinline__ void gemm_tf32_pipe32(const float* __restrict__ A,
                                                 const float* __restrict__ Bm,
                                                 int m0, int n0, float4 acc[2][4])
{
    extern __shared__ float sm[];
    const uint32_t smu = smem_u32(sm);
    const int tid  = threadIdx.x;
    const int lane = tid & 31;
    const int warp = tid >> 5;
    const int wm = (warp >> 1) * 32;
    const int wn = (warp & 1) * 32;
    const int g  = lane >> 2;
    const int t  = lane & 3;

    const float* Ab = A  + (size_t)m0 * 1024;
    const float* Bb = Bm + (size_t)n0 * 1024;

#pragma unroll
    for (int am = 0; am < 2; am++)
#pragma unroll
        for (int an = 0; an < 4; an++)
            acc[am][an] = make_float4(0.f, 0.f, 0.f, 0.f);

    gemm_fill32(smu, Ab, Bb, 0, 0, tid);
    CP_COMMIT();
    gemm_fill32(smu, Ab, Bb, 1, 1, tid);
    CP_COMMIT();

    int stage = 0;
    for (int c = 0; c < 32; ++c) {
        CP_WAIT1();
        __syncthreads();

        if (c + 2 < 32)
            gemm_fill32(smu, Ab, Bb, (stage + 2 >= 3 ? stage - 1 : stage + 2), c + 2, tid);
        CP_COMMIT();

#pragma unroll
        for (int h = 0; h < 2; h++) {
            const float* st = sm + stage * STGF32 + h * HALF_F;

            float4 vb[4];
#pragma unroll
            for (int an = 0; an < 4; an++)
                vb[an] = *(const float4*)(st + 2048 + (wn + an * 8 + g) * 16 + 4 * t);

            float4 vaL[2], vaH[2];
#pragma unroll
            for (int am = 0; am < 2; am++) {
                vaL[am] = *(const float4*)(st + (wm + am * 16 + g)     * 16 + 4 * t);
                vaH[am] = *(const float4*)(st + (wm + am * 16 + g + 8) * 16 + 4 * t);
            }
#pragma unroll
            for (int am = 0; am < 2; am++)
#pragma unroll
                for (int an = 0; an < 4; an++) {
                    mma_tf32(acc[am][an],
                             __float_as_uint(vaL[am].x), __float_as_uint(vaH[am].x),
                             __float_as_uint(vaL[am].y), __float_as_uint(vaH[am].y),
                             __float_as_uint(vb[an].x),  __float_as_uint(vb[an].y));
                    mma_tf32(acc[am][an],
                             __float_as_uint(vaL[am].z), __float_as_uint(vaH[am].z),
                             __float_as_uint(vaL[am].w), __float_as_uint(vaH[am].w),
                             __float_as_uint(vb[an].z),  __float_as_uint(vb[an].w));
                }
        }
        stage = (stage == 2) ? 0 : stage + 1;
    }
}

// ---------------------------------------------------------------------------
// Kernel 1: QKV GEMM. grid (48, 32).
// ---------------------------------------------------------------------------
#define QSCALE 0.18033688011112042f   // 0.125 * log2(e)

__global__ void __launch_bounds__(256, 3) qkv_mma()
{
    const int m0 = blockIdx.y * 128;
    const int n0 = blockIdx.x * 64;
    float4 acc[2][4];
    gemm_tf32_pipe32(g_Xr, g_Wq, m0, n0, acc);

    const int lane = threadIdx.x & 31;
    const int warp = threadIdx.x >> 5;
    const int wm = (warp >> 1) * 32;
    const int wn = (warp & 1) * 32;
    const int g  = lane >> 2;
    const int t  = lane & 3;

#pragma unroll
    for (int an = 0; an < 4; an++) {
        const int ng  = n0 + wn + an * 8;        // n = h*192 + sel*64 + d
        const int grp = ng >> 6;
        const int h   = grp / 3;
        const int sel = grp - 3 * h;
        const int d0  = (ng & 63) + t * 2;
        const float sc = (sel == 0) ? QSCALE : 1.0f;
#pragma unroll
        for (int am = 0; am < 2; am++) {
#pragma unroll
            for (int half = 0; half < 2; half++) {
                const int m = m0 + wm + am * 16 + g + half * 8;
                const int b = m >> 11;
                const int s = m & 2047;
                const float vx = tf32_rna((half ? acc[am][an].z : acc[am][an].x) * sc);
                const float vy = tf32_rna((half ? acc[am][an].w : acc[am][an].y) * sc);
                const size_t bh = (size_t)(b * 16 + h);
                if (sel == 0) {
                    *(float2*)(g_Q + (bh * 2048 + s) * 64 + d0) = make_float2(vx, vy);
                } else if (sel == 1) {
                    float* kp = g_K + (bh * 2048 + s) * 64;
                    kp[perm16(d0)]     = vx;
                    kp[perm16(d0 + 1)] = vy;
                } else {
                    const int sp = perm16(s);
                    float* vp = g_V + (bh * 64 + d0) * 2048;
                    vp[sp]        = vx;
                    vp[2048 + sp] = vy;
                }
            }
        }
    }
}

// ---------------------------------------------------------------------------
// Kernel 3: output projection. grid (16, 32).
// ---------------------------------------------------------------------------
__global__ void __launch_bounds__(256, 3) proj_mma(const float* __restrict__ bias,
                                                   float* __restrict__ out)
{
    const int m0 = blockIdx.y * 128;
    const int n0 = blockIdx.x * 64;
    float4 acc[2][4];
    gemm_tf32_pipe32(g_O, g_Wp, m0, n0, acc);

    const int lane = threadIdx.x & 31;
    const int warp = threadIdx.x >> 5;
    const int wm = (warp >> 1) * 32;
    const int wn = (warp & 1) * 32;
    const int g  = lane >> 2;
    const int t  = lane & 3;

#pragma unroll
    for (int an = 0; an < 4; an++) {
        const int ng = n0 + wn + an * 8 + t * 2;
        const float2 bi = *(const float2*)(bias + ng);
#pragma unroll
        for (int am = 0; am < 2; am++) {
#pragma unroll
            for (int half = 0; half < 2; half++) {
                const int m = m0 + wm + am * 16 + g + half * 8;
                float2 v;
                v.x = (half ? acc[am][an].z : acc[am][an].x) + bi.x;
                v.y = (half ? acc[am][an].w : acc[am][an].y) + bi.y;
                *(float2*)(out + (size_t)m * 1024 + ng) = v;
            }
        }
    }
}

// ============================================================================
// Kernel 2: tensor-core causal flash attention — PAIR-FUSED softmax.
// Round-12 geometry (grid (16,32), 256 thr, 128-row q-tile, pairs of 64-col
// kv-tiles, 2 pair-buffers, one barrier per pair) but: S0 and S1 MMAs issued
// back-to-back, then ONE combined online-softmax over both tiles (single
// rescale per pair, 2x chain ILP), then PV0, PV1.
// ============================================================================
#define KVSTR 80
#define TILEF (64*KVSTR)            // 5120 floats per tile slot
#define PAIRB (2*TILEF)             // 10240 floats per pair buffer
#define OFF_V (2*PAIRB)
#define OFF_P (OFF_V + 2*PAIRB)     // 40960
#define PSTRD 68
#define FA_SMEM_BYTES ((OFF_P + 128*PSTRD) * 4)   // 198656

__global__ void __launch_bounds__(256, 1) flash_attn_tc()
{
    extern __shared__ float sm[];
    const uint32_t smu = smem_u32(sm);
    const int tid  = threadIdx.x;
    const int lane = tid & 31;
    const int warp = tid >> 5;
    const int g  = lane >> 2;
    const int t4 = lane & 3;
    const int qt = 15 - (int)blockIdx.x;
    const int bh = blockIdx.y;
    const int q0 = qt * 128;
    const int wr = warp * 16;
    const int npair = qt + 1;

    const float* Qg = g_Q + (size_t)bh * S_ * 64;
    const float* Kg = g_K + (size_t)bh * S_ * 64;
    const float* Vg = g_V + (size_t)bh * 64 * S_;   // transposed [d][s]

    const int fr = tid >> 2;
    const int fc = (tid & 3) * 16;

    // prefetch pair 0 (tiles 0,1) into pair buffer 0
#pragma unroll
    for (int u = 0; u < 2; u++) {
        const int kv = u * 64;
        const float* ks = Kg + (size_t)(kv + fr) * 64 + fc;
        const float* vs = Vg + (size_t)fr * 2048 + kv + fc;
        const uint32_t kd = smu + (uint32_t)(u * TILEF + fr * KVSTR + fc) * 4;
        const uint32_t vd = smu + (uint32_t)(OFF_V + u * TILEF + fr * KVSTR + fc) * 4;
#pragma unroll
        for (int j = 0; j < 4; j++) {
            cp16(kd + j * 16, ks + j * 4);
            cp16(vd + j * 16, vs + j * 4);
        }
    }
    CP_COMMIT();

    // stage Q tile into P region (coalesced), then pull warp fragments
    {
        const int r  = tid >> 1;
        const int c0 = (tid & 1) * 32;
        const float* src = Qg + (size_t)(q0 + r) * 64 + c0;
        float* dst = sm + OFF_P + r * PSTRD + c0;
#pragma unroll
        for (int j = 0; j < 8; j++)
            *(float4*)(dst + j * 4) = *(const float4*)(src + j * 4);
    }
    __syncthreads();

    uint32_t qf[8][4];
#pragma unroll
    for (int kk = 0; kk < 8; kk++) {
        const float* p = sm + OFF_P + (wr + g) * PSTRD + kk * 8 + t4;
        qf[kk][0] = __float_as_uint(p[0]);
        qf[kk][1] = __float_as_uint(p[8 * PSTRD]);
        qf[kk][2] = __float_as_uint(p[4]);
        qf[kk][3] = __float_as_uint(p[8 * PSTRD + 4]);
    }

    float m2[2] = {-1e30f, -1e30f};
    float l2[2] = {0.f, 0.f};
    float4 of[8];
#pragma unroll
    for (int an = 0; an < 8; an++) of[an] = make_float4(0.f, 0.f, 0.f, 0.f);

    const int limit = q0 + wr + 15;     // last live row of this warp

    for (int pp = 0; pp < npair; pp++) {
        CP_WAIT0();            // pair pp resident
        __syncthreads();       // one barrier per pair

        if (pp + 1 < npair) {  // prefetch pair pp+1 into the other buffer
            const int pb = (pp + 1) & 1;
#pragma unroll
            for (int u = 0; u < 2; u++) {
                const int kv = (pp + 1) * 128 + u * 64;
                const float* ks = Kg + (size_t)(kv + fr) * 64 + fc;
                const float* vs = Vg + (size_t)fr * 2048 + kv + fc;
                const uint32_t kd = smu + (uint32_t)(pb * PAIRB + u * TILEF + fr * KVSTR + fc) * 4;
                const uint32_t vd = smu + (uint32_t)(OFF_V + pb * PAIRB + u * TILEF + fr * KVSTR + fc) * 4;
#pragma unroll
                for (int j = 0; j < 4; j++) {
                    cp16(kd + j * 16, ks + j * 4);
                    cp16(vd + j * 16, vs + j * 4);
                }
            }
        }
        CP_COMMIT();           // uniform commit (possibly empty)

        const int kv0 = pp * 128;
        if (kv0 > limit) continue;          // whole pair dead for this warp
        const int kv1 = kv0 + 64;
        const bool live1 = (kv1 <= limit);

        const float* K0 = sm + (pp & 1) * PAIRB;
        const float* V0 = sm + OFF_V + (pp & 1) * PAIRB;
        const float* K1 = K0 + TILEF;
        const float* V1 = V0 + TILEF;

        // ---- S0 = Q @ K0^T ----
        float4 sf0[8], sf1[8];
#pragma unroll
        for (int an = 0; an < 8; an++) sf0[an] = make_float4(0.f, 0.f, 0.f, 0.f);
#pragma unroll
        for (int b = 0; b < 4; b++)
#pragma unroll
            for (int an = 0; an < 8; an++) {
                const float4 kv4 = *(const float4*)(K0 + (an * 8 + g) * KVSTR + 16 * b + 4 * t4);
                mma_tf32(sf0[an], qf[2*b][0], qf[2*b][1], qf[2*b][2], qf[2*b][3],
                         __float_as_uint(kv4.x), __float_as_uint(kv4.y));
                mma_tf32(sf0[an], qf[2*b+1][0], qf[2*b+1][1], qf[2*b+1][2], qf[2*b+1][3],
                         __float_as_uint(kv4.z), __float_as_uint(kv4.w));
            }

        // ---- S1 = Q @ K1^T (or dead) ----
        if (live1) {
#pragma unroll
            for (int an = 0; an < 8; an++) sf1[an] = make_float4(0.f, 0.f, 0.f, 0.f);
#pragma unroll
            for (int b = 0; b < 4; b++)
#pragma unroll
                for (int an = 0; an < 8; an++) {
                    const float4 kv4 = *(const float4*)(K1 + (an * 8 + g) * KVSTR + 16 * b + 4 * t4);
                    mma_tf32(sf1[an], qf[2*b][0], qf[2*b][1], qf[2*b][2], qf[2*b][3],
                             __float_as_uint(kv4.x), __float_as_uint(kv4.y));
                    mma_tf32(sf1[an], qf[2*b+1][0], qf[2*b+1][1], qf[2*b+1][2], qf[2*b+1][3],
                             __float_as_uint(kv4.z), __float_as_uint(kv4.w));
                }
        } else {
#pragma unroll
            for (int an = 0; an < 8; an++)
                sf1[an] = make_float4(-1e30f, -1e30f, -1e30f, -1e30f);
        }

        // ---- causal masks (near-diagonal only) ----
        const int r0 = q0 + wr + g;
        const int r1 = r0 + 8;
        if (kv0 + 63 > q0 + wr) {
#pragma unroll
            for (int an = 0; an < 8; an++) {
                const int col = kv0 + an * 8 + 2 * t4;
                if (col     > r0) sf0[an].x = -1e30f;
                if (col + 1 > r0) sf0[an].y = -1e30f;
                if (col     > r1) sf0[an].z = -1e30f;
                if (col + 1 > r1) sf0[an].w = -1e30f;
            }
        }
        if (live1 && (kv1 + 63 > q0 + wr)) {
#pragma unroll
            for (int an = 0; an < 8; an++) {
                const int col = kv1 + an * 8 + 2 * t4;
                if (col     > r0) sf1[an].x = -1e30f;
                if (col + 1 > r0) sf1[an].y = -1e30f;
                if (col     > r1) sf1[an].z = -1e30f;
                if (col + 1 > r1) sf1[an].w = -1e30f;
            }
        }

        // ---- combined online softmax over BOTH tiles (one rescale/pair) ----
        float mt0 = -1e30f, mt1 = -1e30f;
#pragma unroll
        for (int an = 0; an < 8; an++) {
            mt0 = fmaxf(mt0, fmaxf(fmaxf(sf0[an].x, sf0[an].y), fmaxf(sf1[an].x, sf1[an].y)));
            mt1 = fmaxf(mt1, fmaxf(fmaxf(sf0[an].z, sf0[an].w), fmaxf(sf1[an].z, sf1[an].w)));
        }
        mt0 = fmaxf(mt0, __shfl_xor_sync(0xffffffffu, mt0, 1));
        mt0 = fmaxf(mt0, __shfl_xor_sync(0xffffffffu, mt0, 2));
        mt1 = fmaxf(mt1, __shfl_xor_sync(0xffffffffu, mt1, 1));
        mt1 = fmaxf(mt1, __shfl_xor_sync(0xffffffffu, mt1, 2));

        const float mn0 = fmaxf(m2[0], mt0);
        const float mn1 = fmaxf(m2[1], mt1);
        const float a0 = exp2p(m2[0] - mn0);
        const float a1 = exp2p(m2[1] - mn1);
        m2[0] = mn0; m2[1] = mn1;

        float s0 = 0.f, s1 = 0.f;
#pragma unroll
        for (int an = 0; an < 8; an++) {
            sf0[an].x = tf32_rna(exp2p(sf0[an].x - mn0));
            sf0[an].y = tf32_rna(exp2p(sf0[an].y - mn0));
            sf0[an].z = tf32_rna(exp2p(sf0[an].z - mn1));
            sf0[an].w = tf32_rna(exp2p(sf0[an].w - mn1));
            sf1[an].x = tf32_rna(exp2p(sf1[an].x - mn0));
            sf1[an].y = tf32_rna(exp2p(sf1[an].y - mn0));
            sf1[an].z = tf32_rna(exp2p(sf1[an].z - mn1));
            sf1[an].w = tf32_rna(exp2p(sf1[an].w - mn1));
            s0 += (sf0[an].x + sf0[an].y) + (sf1[an].x + sf1[an].y);
            s1 += (sf0[an].z + sf0[an].w) + (sf1[an].z + sf1[an].w);
        }
        s0 += __shfl_xor_sync(0xffffffffu, s0, 1);
        s0 += __shfl_xor_sync(0xffffffffu, s0, 2);
        s1 += __shfl_xor_sync(0xffffffffu, s1, 1);
        s1 += __shfl_xor_sync(0xffffffffu, s1, 2);
        l2[0] = l2[0] * a0 + s0;
        l2[1] = l2[1] * a1 + s1;

#pragma unroll
        for (int an = 0; an < 8; an++) {
            of[an].x *= a0; of[an].y *= a0;
            of[an].z *= a1; of[an].w *= a1;
        }

        // ---- PV0 ----
        {
            float* pw = sm + OFF_P + (wr + g) * PSTRD;
#pragma unroll
            for (int an = 0; an < 8; an++) {
                *(float2*)(pw + an * 8 + 2 * t4) = make_float2(sf0[an].x, sf0[an].y);
                *(float2*)(pw + 8 * PSTRD + an * 8 + 2 * t4) = make_float2(sf0[an].z, sf0[an].w);
            }
        }
        __syncwarp();
#pragma unroll
        for (int b = 0; b < 4; b++) {
            const float* ap = sm + OFF_P + (wr + g) * PSTRD + 16 * b + t4;
            const uint32_t A00 = __float_as_uint(ap[0]);
            const uint32_t A01 = __float_as_uint(ap[8 * PSTRD]);
            const uint32_t A02 = __float_as_uint(ap[4]);
            const uint32_t A03 = __float_as_uint(ap[8 * PSTRD + 4]);
            const uint32_t A10 = __float_as_uint(ap[8]);
            const uint32_t A11 = __float_as_uint(ap[8 * PSTRD + 8]);
            const uint32_t A12 = __float_as_uint(ap[12]);
            const uint32_t A13 = __float_as_uint(ap[8 * PSTRD + 12]);
#pragma unroll
            for (int an = 0; an < 8; an++) {
                const float4 vv = *(const float4*)(V0 + (an * 8 + g) * KVSTR + 16 * b + 4 * t4);
                mma_tf32(of[an], A00, A01, A02, A03,
                         __float_as_uint(vv.x), __float_as_uint(vv.y));
                mma_tf32(of[an], A10, A11, A12, A13,
                         __float_as_uint(vv.z), __float_as_uint(vv.w));
            }
        }

        // ---- PV1 (skip entirely if tile1 dead) ----
        if (live1) {
            __syncwarp();   // PV0 reads done before overwriting P rows
            {
                float* pw = sm + OFF_P + (wr + g) * PSTRD;
#pragma unroll
                for (int an = 0; an < 8; an++) {
                    *(float2*)(pw + an * 8 + 2 * t4) = make_float2(sf1[an].x, sf1[an].y);
                    *(float2*)(pw + 8 * PSTRD + an * 8 + 2 * t4) = make_float2(sf1[an].z, sf1[an].w);
                }
            }
            __syncwarp();
#pragma unroll
            for (int b = 0; b < 4; b++) {
                const float* ap = sm + OFF_P + (wr + g) * PSTRD + 16 * b + t4;
                const uint32_t A00 = __float_as_uint(ap[0]);
                const uint32_t A01 = __float_as_uint(ap[8 * PSTRD]);
                const uint32_t A02 = __float_as_uint(ap[4]);
                const uint32_t A03 = __float_as_uint(ap[8 * PSTRD + 4]);
                const uint32_t A10 = __float_as_uint(ap[8]);
                const uint32_t A11 = __float_as_uint(ap[8 * PSTRD + 8]);
                const uint32_t A12 = __float_as_uint(ap[12]);
                const uint32_t A13 = __float_as_uint(ap[8 * PSTRD + 12]);
#pragma unroll
                for (int an = 0; an < 8; an++) {
                    const float4 vv = *(const float4*)(V1 + (an * 8 + g) * KVSTR + 16 * b + 4 * t4);
                    mma_tf32(of[an], A00, A01, A02, A03,
                             __float_as_uint(vv.x), __float_as_uint(vv.y));
                    mma_tf32(of[an], A10, A11, A12, A13,
                             __float_as_uint(vv.z), __float_as_uint(vv.w));
                }
            }
        }
    }

    // epilogue: normalize, tf32-round, write g_O d-PERMUTED (proj A layout)
    const int b = bh >> 4;
    const int h = bh & 15;
    const float i0 = 1.0f / l2[0];
    const float i1 = 1.0f / l2[1];
    const int r0 = q0 + wr + g;
    const int r1 = r0 + 8;
    float* o0 = g_O + ((size_t)b * 2048 + r0) * 1024 + h * 64;
    float* o1 = g_O + ((size_t)b * 2048 + r1) * 1024 + h * 64;
#pragma unroll
    for (int an = 0; an < 8; an++) {
        const int c0 = an * 8 + 2 * t4;
        const int p0 = perm16(c0);
        const int p1 = perm16(c0 + 1);
        o0[p0] = tf32_rna(of[an].x * i0);
        o0[p1] = tf32_rna(of[an].y * i0);
        o1[p0] = tf32_rna(of[an].z * i1);
        o1[p1] = tf32_rna(of[an].w * i1);
    }
}

// ---------------------------------------------------------------------------
extern "C" void kernel_launch(void* const* d_in, const int* in_sizes, int n_in,
                              void* d_out, int out_size)
{
    const float* x      = (const float*)d_in[0];  // (2,2048,1024)
    const float* w_qkv  = (const float*)d_in[1];  // (3072,1024)
    const float* w_proj = (const float*)d_in[2];  // (1024,1024)
    const float* b_proj = (const float*)d_in[3];  // (1024,)
    float* out = (float*)d_out;

    cudaFuncSetAttribute(flash_attn_tc, cudaFuncAttributeMaxDynamicSharedMemorySize,
                         FA_SMEM_BYTES);
    cudaFuncSetAttribute(qkv_mma, cudaFuncAttributeMaxDynamicSharedMemorySize,
                         GEMM_SMEM_BYTES);
    cudaFuncSetAttribute(proj_mma, cudaFuncAttributeMaxDynamicSharedMemorySize,
                         GEMM_SMEM_BYTES);

    round_perm_all<<<592, 256>>>(x, w_qkv, w_proj);

    qkv_mma<<<dim3(48, 32), 256, GEMM_SMEM_BYTES>>>();
    flash_attn_tc<<<dim3(16, 32), 256, FA_SMEM_BYTES>>>();
    proj_mma<<<dim3(16, 32), 256, GEMM_SMEM_BYTES>>>(b_proj, out);
}